// round 3
// baseline (speedup 1.0000x reference)
#include <cuda_runtime.h>
#include <math.h>
#include <stddef.h>

#define N_NODES 50000
#define N_EDGES 800000
#define D 64
#define HID 128
#define IN_F 192
#define ET 64
#define BLOCK 256
#define NBLK 152

// shared memory layout (in floats)
#define OFF_W1 0                 // 192*128 = 24576
#define OFF_W2 24576             // 128*64  = 8192
#define OFF_B1 32768             // 128
#define OFF_B2 32896             // 64
#define OFF_G  32960             // 64
#define OFF_BETA 33024           // 64
#define XS 196                   // padded row stride for X (192 data + 4 pad)
#define HS 132                   // padded row stride for H (128 data + 4 pad)
#define OFF_X 33088              // 64*196 = 12544
#define OFF_H 45632              // 64*132 = 8448
#define SMEM_FLOATS 54080
#define SMEM_BYTES (SMEM_FLOATS * 4)   // 216320 B

// scratch for segment-mean aggregation (device globals: no allocation allowed)
__device__ __align__(16) float g_acc_u[N_NODES * D];
__device__ __align__(16) float g_acc_v[N_NODES * D];
__device__ float g_cnt_s[N_NODES];
__device__ float g_cnt_d[N_NODES];

__device__ __forceinline__ float gelu_tanh(float x) {
    // jax.nn.gelu(approximate=True)
    float x3 = x * x * x;
    return 0.5f * x * (1.0f + tanhf(0.7978845608028654f * (x + 0.044715f * x3)));
}

__global__ void zero_scratch_kernel() {
    int i = blockIdx.x * blockDim.x + threadIdx.x;
    int stride = gridDim.x * blockDim.x;
    const float4 z = make_float4(0.f, 0.f, 0.f, 0.f);
    for (int j = i; j < N_NODES * D / 4; j += stride) {
        ((float4*)g_acc_u)[j] = z;
        ((float4*)g_acc_v)[j] = z;
    }
    for (int j = i; j < N_NODES; j += stride) {
        g_cnt_s[j] = 0.f;
        g_cnt_d[j] = 0.f;
    }
}

// One kernel template handles both the edge MLP (EDGE=true: gather
// ndata[src]|ndata[dst]|edata, epilogue does scatter-add) and the node MLP
// (EDGE=false: gather mean_u|mean_v|ndata).
template <bool EDGE>
__global__ __launch_bounds__(BLOCK, 1)
void mlp_kernel(const float* __restrict__ ndata,
                const float* __restrict__ edata,
                const int* __restrict__ src,
                const int* __restrict__ dst,
                const float* __restrict__ W1,
                const float* __restrict__ b1,
                const float* __restrict__ W2,
                const float* __restrict__ b2,
                const float* __restrict__ gam,
                const float* __restrict__ beta,
                float* __restrict__ out,
                int count) {
    extern __shared__ float sm[];
    float* sW1 = sm + OFF_W1;
    float* sW2 = sm + OFF_W2;
    float* sB1 = sm + OFF_B1;
    float* sB2 = sm + OFF_B2;
    float* sG  = sm + OFF_G;
    float* sBt = sm + OFF_BETA;
    float* sX  = sm + OFF_X;
    float* sH  = sm + OFF_H;
    const int tid = threadIdx.x;

    // stage weights once per (persistent) block
    for (int i = tid; i < IN_F * HID; i += BLOCK) sW1[i] = W1[i];
    for (int i = tid; i < HID * D; i += BLOCK) sW2[i] = W2[i];
    for (int i = tid; i < HID; i += BLOCK) sB1[i] = b1[i];
    for (int i = tid; i < D; i += BLOCK) {
        sB2[i] = b2[i];
        sG[i] = gam[i];
        sBt[i] = beta[i];
    }
    __syncthreads();

    const float4* nd4 = (const float4*)ndata;
    const float4* ed4 = (const float4*)edata;

    const int ntiles = (count + ET - 1) / ET;
    for (int tile = blockIdx.x; tile < ntiles; tile += gridDim.x) {
        const int e0 = tile * ET;

        // ---- gather X tile: [ET][192] (float4 granularity: 48 per row) ----
        for (int j = tid; j < ET * 48; j += BLOCK) {
            int e = j / 48, seg = j % 48;
            int idx = e0 + e;
            float4 v = make_float4(0.f, 0.f, 0.f, 0.f);
            if (idx < count) {
                if (EDGE) {
                    if (seg < 16)      v = nd4[(size_t)src[idx] * 16 + seg];
                    else if (seg < 32) v = nd4[(size_t)dst[idx] * 16 + (seg - 16)];
                    else               v = ed4[(size_t)idx * 16 + (seg - 32)];
                } else {
                    if (seg < 16) {
                        float inv = 1.f / fmaxf(g_cnt_s[idx], 1.f);
                        float4 a = ((const float4*)g_acc_u)[(size_t)idx * 16 + seg];
                        v = make_float4(a.x * inv, a.y * inv, a.z * inv, a.w * inv);
                    } else if (seg < 32) {
                        float inv = 1.f / fmaxf(g_cnt_d[idx], 1.f);
                        float4 a = ((const float4*)g_acc_v)[(size_t)idx * 16 + (seg - 16)];
                        v = make_float4(a.x * inv, a.y * inv, a.z * inv, a.w * inv);
                    } else {
                        v = nd4[(size_t)idx * 16 + (seg - 32)];
                    }
                }
            }
            ((float4*)sX)[e * (XS / 4) + seg] = v;
        }
        __syncthreads();

        // ---- GEMM1: H[64][128] = gelu(X @ W1 + b1) ----
        {
            const int r = tid >> 4;   // 0..15, 4 edges each
            const int c = tid & 15;   // 8 cols each
            float acc[4][8];
            #pragma unroll
            for (int j = 0; j < 8; j++) {
                float bv = sB1[c * 8 + j];
                #pragma unroll
                for (int i = 0; i < 4; i++) acc[i][j] = bv;
            }
            const float4* w4 = (const float4*)sW1;
            #pragma unroll 4
            for (int k = 0; k < IN_F; k++) {
                float x0 = sX[(r * 4 + 0) * XS + k];
                float x1 = sX[(r * 4 + 1) * XS + k];
                float x2 = sX[(r * 4 + 2) * XS + k];
                float x3 = sX[(r * 4 + 3) * XS + k];
                float4 wa = w4[k * 32 + c * 2];
                float4 wb = w4[k * 32 + c * 2 + 1];
                float w[8] = {wa.x, wa.y, wa.z, wa.w, wb.x, wb.y, wb.z, wb.w};
                #pragma unroll
                for (int j = 0; j < 8; j++) {
                    acc[0][j] = fmaf(x0, w[j], acc[0][j]);
                    acc[1][j] = fmaf(x1, w[j], acc[1][j]);
                    acc[2][j] = fmaf(x2, w[j], acc[2][j]);
                    acc[3][j] = fmaf(x3, w[j], acc[3][j]);
                }
            }
            #pragma unroll
            for (int i = 0; i < 4; i++) {
                float4 o0 = make_float4(gelu_tanh(acc[i][0]), gelu_tanh(acc[i][1]),
                                        gelu_tanh(acc[i][2]), gelu_tanh(acc[i][3]));
                float4 o1 = make_float4(gelu_tanh(acc[i][4]), gelu_tanh(acc[i][5]),
                                        gelu_tanh(acc[i][6]), gelu_tanh(acc[i][7]));
                float4* hp = (float4*)(sH + (r * 4 + i) * HS + c * 8);
                hp[0] = o0;
                hp[1] = o1;
            }
        }
        __syncthreads();

        // ---- GEMM2 + LayerNorm + writeout (+ scatter for EDGE) ----
        {
            const int e = tid >> 2;   // 0..63
            const int c2 = tid & 3;   // 16 cols each
            float acc[16];
            #pragma unroll
            for (int j = 0; j < 16; j++) acc[j] = sB2[c2 * 16 + j];
            const float4* w4 = (const float4*)sW2;
            #pragma unroll 4
            for (int k = 0; k < HID; k++) {
                float h = sH[e * HS + k];
                #pragma unroll
                for (int q = 0; q < 4; q++) {
                    float4 w = w4[k * 16 + c2 * 4 + q];
                    acc[q * 4 + 0] = fmaf(h, w.x, acc[q * 4 + 0]);
                    acc[q * 4 + 1] = fmaf(h, w.y, acc[q * 4 + 1]);
                    acc[q * 4 + 2] = fmaf(h, w.z, acc[q * 4 + 2]);
                    acc[q * 4 + 3] = fmaf(h, w.w, acc[q * 4 + 3]);
                }
            }
            float s = 0.f, sq = 0.f;
            #pragma unroll
            for (int j = 0; j < 16; j++) { s += acc[j]; sq += acc[j] * acc[j]; }
            s  += __shfl_xor_sync(0xffffffffu, s, 1);
            sq += __shfl_xor_sync(0xffffffffu, sq, 1);
            s  += __shfl_xor_sync(0xffffffffu, s, 2);
            sq += __shfl_xor_sync(0xffffffffu, sq, 2);
            float mean = s * (1.f / 64.f);
            float var  = sq * (1.f / 64.f) - mean * mean;
            float rstd = rsqrtf(var + 1e-5f);

            int idx = e0 + e;
            if (idx < count) {
                float o[16];
                #pragma unroll
                for (int j = 0; j < 16; j++)
                    o[j] = (acc[j] - mean) * rstd * sG[c2 * 16 + j] + sBt[c2 * 16 + j];
                float4* op = (float4*)(out + (size_t)idx * D + c2 * 16);
                op[0] = make_float4(o[0], o[1], o[2], o[3]);
                op[1] = make_float4(o[4], o[5], o[6], o[7]);
                op[2] = make_float4(o[8], o[9], o[10], o[11]);
                op[3] = make_float4(o[12], o[13], o[14], o[15]);
                if (EDGE) {
                    int sN = src[idx], dN = dst[idx];
                    float* au = g_acc_u + (size_t)sN * D + c2 * 16;
                    float* av = g_acc_v + (size_t)dN * D + c2 * 16;
                    #pragma unroll
                    for (int j = 0; j < 16; j++) {
                        atomicAdd(au + j, o[j]);
                        atomicAdd(av + j, o[j]);
                    }
                    if (c2 == 0) {
                        atomicAdd(&g_cnt_s[sN], 1.f);
                        atomicAdd(&g_cnt_d[dN], 1.f);
                    }
                }
            }
        }
        __syncthreads();
    }
}

extern "C" void kernel_launch(void* const* d_in, const int* in_sizes, int n_in,
                              void* d_out, int out_size) {
    const float* ndata = (const float*)d_in[0];
    const float* edata = (const float*)d_in[1];
    const int* src = (const int*)d_in[2];
    const int* dst = (const int*)d_in[3];
    const float* eW1 = (const float*)d_in[4];
    const float* eb1 = (const float*)d_in[5];
    const float* eW2 = (const float*)d_in[6];
    const float* eb2 = (const float*)d_in[7];
    const float* eg = (const float*)d_in[8];
    const float* ebeta = (const float*)d_in[9];
    const float* nW1 = (const float*)d_in[10];
    const float* nb1 = (const float*)d_in[11];
    const float* nW2 = (const float*)d_in[12];
    const float* nb2 = (const float*)d_in[13];
    const float* ng = (const float*)d_in[14];
    const float* nbeta = (const float*)d_in[15];

    float* out = (float*)d_out;
    float* out_nodes = out;                       // ndata_new first
    float* out_edges = out + (size_t)N_NODES * D; // then edata_new

    // allow >48KB dynamic smem (deterministic, host-side, capture-safe)
    void (*kE)(const float*, const float*, const int*, const int*,
               const float*, const float*, const float*, const float*,
               const float*, const float*, float*, int) = mlp_kernel<true>;
    void (*kN)(const float*, const float*, const int*, const int*,
               const float*, const float*, const float*, const float*,
               const float*, const float*, float*, int) = mlp_kernel<false>;
    cudaFuncSetAttribute((const void*)kE, cudaFuncAttributeMaxDynamicSharedMemorySize, SMEM_BYTES);
    cudaFuncSetAttribute((const void*)kN, cudaFuncAttributeMaxDynamicSharedMemorySize, SMEM_BYTES);

    zero_scratch_kernel<<<1024, 256>>>();
    kE<<<NBLK, BLOCK, SMEM_BYTES>>>(ndata, edata, src, dst,
                                    eW1, eb1, eW2, eb2, eg, ebeta,
                                    out_edges, N_EDGES);
    kN<<<NBLK, BLOCK, SMEM_BYTES>>>(ndata, nullptr, nullptr, nullptr,
                                    nW1, nb1, nW2, nb2, ng, nbeta,
                                    out_nodes, N_NODES);
}

// round 4
// speedup vs baseline: 1.4034x; 1.4034x over previous
#include <cuda_runtime.h>
#include <math.h>
#include <stddef.h>

#define N_NODES 50000
#define N_EDGES 800000
#define D 64
#define HID 128
#define IN_F 192
#define ET 64
#define BLOCK 512
#define NBLK 152

// shared memory layout (in floats)
#define OFF_W1 0                 // 192*128 = 24576
#define OFF_W2 24576             // 128*64  = 8192
#define OFF_B1 32768             // 128
#define OFF_B2 32896             // 64
#define OFF_G  32960             // 64
#define OFF_BETA 33024           // 64
#define XS 196                   // padded row stride for X (192 data + 4 pad), mult of 4
#define HS 132                   // padded row stride for H (128 data + 4 pad), mult of 4
#define OFF_X 33088              // 64*196 = 12544
#define OFF_H 45632              // 64*132 = 8448
#define SMEM_FLOATS 54080
#define SMEM_BYTES (SMEM_FLOATS * 4)   // 216320 B

// scratch for segment-mean aggregation (device globals: no allocation allowed)
__device__ __align__(16) float g_acc_u[N_NODES * D];
__device__ __align__(16) float g_acc_v[N_NODES * D];
__device__ float g_cnt_s[N_NODES];
__device__ float g_cnt_d[N_NODES];

__device__ __forceinline__ float gelu_tanh(float x) {
    float x3 = x * x * x;
    return 0.5f * x * (1.0f + tanhf(0.7978845608028654f * (x + 0.044715f * x3)));
}

__device__ __forceinline__ void red_add_v4(float* addr, float a, float b, float c, float d) {
    asm volatile("red.global.add.v4.f32 [%0], {%1,%2,%3,%4};"
                 :: "l"(addr), "f"(a), "f"(b), "f"(c), "f"(d) : "memory");
}

__global__ void zero_scratch_kernel() {
    int i = blockIdx.x * blockDim.x + threadIdx.x;
    int stride = gridDim.x * blockDim.x;
    const float4 z = make_float4(0.f, 0.f, 0.f, 0.f);
    for (int j = i; j < N_NODES * D / 4; j += stride) {
        ((float4*)g_acc_u)[j] = z;
        ((float4*)g_acc_v)[j] = z;
    }
    for (int j = i; j < N_NODES; j += stride) {
        g_cnt_s[j] = 0.f;
        g_cnt_d[j] = 0.f;
    }
}

// EDGE=true: gather ndata[src]|ndata[dst]|edata, epilogue scatter-adds into
// node accumulators. EDGE=false: gather mean_u|mean_v|ndata.
template <bool EDGE>
__global__ __launch_bounds__(BLOCK, 1)
void mlp_kernel(const float* __restrict__ ndata,
                const float* __restrict__ edata,
                const int* __restrict__ src,
                const int* __restrict__ dst,
                const float* __restrict__ W1,
                const float* __restrict__ b1,
                const float* __restrict__ W2,
                const float* __restrict__ b2,
                const float* __restrict__ gam,
                const float* __restrict__ beta,
                float* __restrict__ out,
                int count) {
    extern __shared__ float sm[];
    float* sW1 = sm + OFF_W1;
    float* sW2 = sm + OFF_W2;
    float* sB1 = sm + OFF_B1;
    float* sB2 = sm + OFF_B2;
    float* sG  = sm + OFF_G;
    float* sBt = sm + OFF_BETA;
    float* sX  = sm + OFF_X;
    float* sH  = sm + OFF_H;
    const int tid = threadIdx.x;

    // stage weights once per (persistent) block
    for (int i = tid; i < IN_F * HID; i += BLOCK) sW1[i] = W1[i];
    for (int i = tid; i < HID * D; i += BLOCK) sW2[i] = W2[i];
    for (int i = tid; i < HID; i += BLOCK) sB1[i] = b1[i];
    for (int i = tid; i < D; i += BLOCK) {
        sB2[i] = b2[i];
        sG[i] = gam[i];
        sBt[i] = beta[i];
    }
    __syncthreads();

    const float4* nd4 = (const float4*)ndata;
    const float4* ed4 = (const float4*)edata;

    const int ntiles = (count + ET - 1) / ET;
    for (int tile = blockIdx.x; tile < ntiles; tile += gridDim.x) {
        const int e0 = tile * ET;

        // ---- gather X tile: [ET][192] as float4 (48 per row), 6 per thread ----
        #pragma unroll
        for (int jj = 0; jj < 6; jj++) {
            int j = tid + jj * BLOCK;          // 0..3071
            int e = j / 48, seg = j % 48;
            int idx = e0 + e;
            float4 v = make_float4(0.f, 0.f, 0.f, 0.f);
            if (EDGE || idx < count) {
                if (EDGE) {
                    if (seg < 16)      v = nd4[(size_t)src[idx] * 16 + seg];
                    else if (seg < 32) v = nd4[(size_t)dst[idx] * 16 + (seg - 16)];
                    else               v = ed4[(size_t)idx * 16 + (seg - 32)];
                } else {
                    if (seg < 16) {
                        float inv = 1.f / fmaxf(g_cnt_s[idx], 1.f);
                        float4 a = ((const float4*)g_acc_u)[(size_t)idx * 16 + seg];
                        v = make_float4(a.x * inv, a.y * inv, a.z * inv, a.w * inv);
                    } else if (seg < 32) {
                        float inv = 1.f / fmaxf(g_cnt_d[idx], 1.f);
                        float4 a = ((const float4*)g_acc_v)[(size_t)idx * 16 + (seg - 16)];
                        v = make_float4(a.x * inv, a.y * inv, a.z * inv, a.w * inv);
                    } else {
                        v = nd4[(size_t)idx * 16 + (seg - 32)];
                    }
                }
            }
            ((float4*)sX)[e * (XS / 4) + seg] = v;
        }
        __syncthreads();

        // ---- GEMM1: H[64][128] = gelu(X @ W1 + b1) ----
        // 512 threads: rp = tid>>4 -> rows {2rp, 2rp+1}; c = tid&15 -> 8 cols
        {
            const int rp = tid >> 4;
            const int c = tid & 15;
            const float4* x4a = (const float4*)(sX + (rp * 2 + 0) * XS);
            const float4* x4b = (const float4*)(sX + (rp * 2 + 1) * XS);
            float acc[2][8];
            #pragma unroll
            for (int j = 0; j < 8; j++) {
                float bv = sB1[c * 8 + j];
                acc[0][j] = bv;
                acc[1][j] = bv;
            }
            const float4* w4 = (const float4*)sW1;
            #pragma unroll 2
            for (int k4 = 0; k4 < IN_F / 4; k4++) {
                float4 xa = x4a[k4];
                float4 xb = x4b[k4];
                float xs0[4] = {xa.x, xa.y, xa.z, xa.w};
                float xs1[4] = {xb.x, xb.y, xb.z, xb.w};
                #pragma unroll
                for (int kk = 0; kk < 4; kk++) {
                    int k = k4 * 4 + kk;
                    float4 wa = w4[k * 32 + c * 2];
                    float4 wb = w4[k * 32 + c * 2 + 1];
                    float w[8] = {wa.x, wa.y, wa.z, wa.w, wb.x, wb.y, wb.z, wb.w};
                    #pragma unroll
                    for (int j = 0; j < 8; j++) {
                        acc[0][j] = fmaf(xs0[kk], w[j], acc[0][j]);
                        acc[1][j] = fmaf(xs1[kk], w[j], acc[1][j]);
                    }
                }
            }
            #pragma unroll
            for (int i = 0; i < 2; i++) {
                float4 o0 = make_float4(gelu_tanh(acc[i][0]), gelu_tanh(acc[i][1]),
                                        gelu_tanh(acc[i][2]), gelu_tanh(acc[i][3]));
                float4 o1 = make_float4(gelu_tanh(acc[i][4]), gelu_tanh(acc[i][5]),
                                        gelu_tanh(acc[i][6]), gelu_tanh(acc[i][7]));
                float4* hp = (float4*)(sH + (rp * 2 + i) * HS + c * 8);
                hp[0] = o0;
                hp[1] = o1;
            }
        }
        __syncthreads();

        // ---- GEMM2 + LayerNorm + writeout (+ scatter for EDGE) ----
        // e = tid>>3 (0..63), c2 = tid&7 -> 8 cols each
        {
            const int e = tid >> 3;
            const int c2 = tid & 7;
            float acc[8];
            #pragma unroll
            for (int j = 0; j < 8; j++) acc[j] = sB2[c2 * 8 + j];
            const float4* w4 = (const float4*)sW2;
            const float4* h4 = (const float4*)(sH + e * HS);
            #pragma unroll 2
            for (int k4 = 0; k4 < HID / 4; k4++) {
                float4 hv = h4[k4];
                float hs[4] = {hv.x, hv.y, hv.z, hv.w};
                #pragma unroll
                for (int kk = 0; kk < 4; kk++) {
                    int k = k4 * 4 + kk;
                    float4 wa = w4[k * 16 + c2 * 2];
                    float4 wb = w4[k * 16 + c2 * 2 + 1];
                    acc[0] = fmaf(hs[kk], wa.x, acc[0]);
                    acc[1] = fmaf(hs[kk], wa.y, acc[1]);
                    acc[2] = fmaf(hs[kk], wa.z, acc[2]);
                    acc[3] = fmaf(hs[kk], wa.w, acc[3]);
                    acc[4] = fmaf(hs[kk], wb.x, acc[4]);
                    acc[5] = fmaf(hs[kk], wb.y, acc[5]);
                    acc[6] = fmaf(hs[kk], wb.z, acc[6]);
                    acc[7] = fmaf(hs[kk], wb.w, acc[7]);
                }
            }
            float s = 0.f, sq = 0.f;
            #pragma unroll
            for (int j = 0; j < 8; j++) { s += acc[j]; sq += acc[j] * acc[j]; }
            s  += __shfl_xor_sync(0xffffffffu, s, 1);
            sq += __shfl_xor_sync(0xffffffffu, sq, 1);
            s  += __shfl_xor_sync(0xffffffffu, s, 2);
            sq += __shfl_xor_sync(0xffffffffu, sq, 2);
            s  += __shfl_xor_sync(0xffffffffu, s, 4);
            sq += __shfl_xor_sync(0xffffffffu, sq, 4);
            float mean = s * (1.f / 64.f);
            float var  = sq * (1.f / 64.f) - mean * mean;
            float rstd = rsqrtf(var + 1e-5f);

            int idx = e0 + e;
            if (EDGE || idx < count) {
                float o[8];
                #pragma unroll
                for (int j = 0; j < 8; j++)
                    o[j] = (acc[j] - mean) * rstd * sG[c2 * 8 + j] + sBt[c2 * 8 + j];
                float4* op = (float4*)(out + (size_t)idx * D + c2 * 8);
                op[0] = make_float4(o[0], o[1], o[2], o[3]);
                op[1] = make_float4(o[4], o[5], o[6], o[7]);
                if (EDGE) {
                    int sN = src[idx], dN = dst[idx];
                    float* au = g_acc_u + (size_t)sN * D + c2 * 8;
                    float* av = g_acc_v + (size_t)dN * D + c2 * 8;
                    red_add_v4(au,     o[0], o[1], o[2], o[3]);
                    red_add_v4(au + 4, o[4], o[5], o[6], o[7]);
                    red_add_v4(av,     o[0], o[1], o[2], o[3]);
                    red_add_v4(av + 4, o[4], o[5], o[6], o[7]);
                    if (c2 == 0) {
                        atomicAdd(&g_cnt_s[sN], 1.f);
                        atomicAdd(&g_cnt_d[dN], 1.f);
                    }
                }
            }
        }
        __syncthreads();
    }
}

extern "C" void kernel_launch(void* const* d_in, const int* in_sizes, int n_in,
                              void* d_out, int out_size) {
    const float* ndata = (const float*)d_in[0];
    const float* edata = (const float*)d_in[1];
    const int* src = (const int*)d_in[2];
    const int* dst = (const int*)d_in[3];
    const float* eW1 = (const float*)d_in[4];
    const float* eb1 = (const float*)d_in[5];
    const float* eW2 = (const float*)d_in[6];
    const float* eb2 = (const float*)d_in[7];
    const float* eg = (const float*)d_in[8];
    const float* ebeta = (const float*)d_in[9];
    const float* nW1 = (const float*)d_in[10];
    const float* nb1 = (const float*)d_in[11];
    const float* nW2 = (const float*)d_in[12];
    const float* nb2 = (const float*)d_in[13];
    const float* ng = (const float*)d_in[14];
    const float* nbeta = (const float*)d_in[15];

    float* out = (float*)d_out;
    float* out_nodes = out;                       // ndata_new first
    float* out_edges = out + (size_t)N_NODES * D; // then edata_new

    void (*kE)(const float*, const float*, const int*, const int*,
               const float*, const float*, const float*, const float*,
               const float*, const float*, float*, int) = mlp_kernel<true>;
    void (*kN)(const float*, const float*, const int*, const int*,
               const float*, const float*, const float*, const float*,
               const float*, const float*, float*, int) = mlp_kernel<false>;
    cudaFuncSetAttribute((const void*)kE, cudaFuncAttributeMaxDynamicSharedMemorySize, SMEM_BYTES);
    cudaFuncSetAttribute((const void*)kN, cudaFuncAttributeMaxDynamicSharedMemorySize, SMEM_BYTES);

    zero_scratch_kernel<<<1024, 256>>>();
    kE<<<NBLK, BLOCK, SMEM_BYTES>>>(ndata, edata, src, dst,
                                    eW1, eb1, eW2, eb2, eg, ebeta,
                                    out_edges, N_EDGES);
    kN<<<NBLK, BLOCK, SMEM_BYTES>>>(ndata, nullptr, nullptr, nullptr,
                                    nW1, nb1, nW2, nb2, ng, nbeta,
                                    out_nodes, N_NODES);
}

// round 7
// speedup vs baseline: 5.6453x; 4.0225x over previous
#include <cuda_runtime.h>
#include <cuda_bf16.h>
#include <math.h>
#include <stdint.h>
#include <stddef.h>

#define N_NODES 50000
#define N_EDGES 800000
#define D 64
#define HID 128
#define IN_F 192
#define TM 64
#define BLOCK 512
#define NBLK 152

// padded bf16 row strides (row byte base steps by 16 mod 128 -> conflict-free ldmatrix)
#define XSTR 200     // K=192 + 8 pad
#define HSTR 136     // K=128 + 8 pad
#define W1STR 200
#define W2STR 136

// ---- shared memory byte offsets ----
#define W1H_OFF 0            // [128 n][200 k] bf16 = 51200
#define W1L_OFF 51200
#define W2H_OFF 102400       // [64 n][136 k] bf16 = 17408
#define W2L_OFF 119808
#define XH_OFF 137216        // [64 m][200 k] bf16 = 25600
#define XL_OFF 162816
#define HH_OFF 188416        // [64 m][136 k] bf16 = 17408
#define HL_OFF 205824
#define B1_OFF 223232        // b1[128] f32
#define B2_OFF 223744        // b2[64] f32
#define G_OFF 224000
#define BETA_OFF 224256
#define RSUM_OFF 224512      // per-row LN partial sum [64]
#define RSQ_OFF 224768       // per-row LN partial sumsq [64]
#define SMEM_BYTES 225024

// scratch for segment-mean aggregation
__device__ __align__(16) float g_acc_u[N_NODES * D];
__device__ __align__(16) float g_acc_v[N_NODES * D];
__device__ float g_cnt_s[N_NODES];
__device__ float g_cnt_d[N_NODES];

// ---------------- helpers ----------------
__device__ __forceinline__ uint32_t smem_u32(const void* p) {
    uint32_t a;
    asm("{ .reg .u64 t; cvta.to.shared.u64 t, %1; cvt.u32.u64 %0, t; }" : "=r"(a) : "l"(p));
    return a;
}
__device__ __forceinline__ void ldsm4(uint32_t* r, uint32_t addr) {
    asm volatile("ldmatrix.sync.aligned.m8n8.x4.shared.b16 {%0,%1,%2,%3}, [%4];"
                 : "=r"(r[0]), "=r"(r[1]), "=r"(r[2]), "=r"(r[3]) : "r"(addr));
}
__device__ __forceinline__ void ldsm2(uint32_t* r, uint32_t addr) {
    asm volatile("ldmatrix.sync.aligned.m8n8.x2.shared.b16 {%0,%1}, [%2];"
                 : "=r"(r[0]), "=r"(r[1]) : "r"(addr));
}
__device__ __forceinline__ void mma16816(float* d, const uint32_t* a, const uint32_t* b) {
    asm volatile("mma.sync.aligned.m16n8k16.row.col.f32.bf16.bf16.f32 "
                 "{%0,%1,%2,%3}, {%4,%5,%6,%7}, {%8,%9}, {%0,%1,%2,%3};"
                 : "+f"(d[0]), "+f"(d[1]), "+f"(d[2]), "+f"(d[3])
                 : "r"(a[0]), "r"(a[1]), "r"(a[2]), "r"(a[3]), "r"(b[0]), "r"(b[1]));
}
__device__ __forceinline__ void split2(float a, float b, uint32_t& hi, uint32_t& lo) {
    __nv_bfloat16 ah = __float2bfloat16_rn(a), bh = __float2bfloat16_rn(b);
    __nv_bfloat162 h; h.x = ah; h.y = bh;
    hi = *reinterpret_cast<uint32_t*>(&h);
    __nv_bfloat162 l;
    l.x = __float2bfloat16_rn(a - __bfloat162float(ah));
    l.y = __float2bfloat16_rn(b - __bfloat162float(bh));
    lo = *reinterpret_cast<uint32_t*>(&l);
}
__device__ __forceinline__ float gelu_tanh(float x) {
    float x3 = x * x * x;
    return 0.5f * x * (1.0f + tanhf(0.7978845608028654f * (x + 0.044715f * x3)));
}
__device__ __forceinline__ void red_add_v2(float* addr, float a, float b) {
    asm volatile("red.global.add.v2.f32 [%0], {%1,%2};"
                 :: "l"(addr), "f"(a), "f"(b) : "memory");
}

__global__ void zero_scratch_kernel() {
    int i = blockIdx.x * blockDim.x + threadIdx.x;
    int stride = gridDim.x * blockDim.x;
    const float4 z = make_float4(0.f, 0.f, 0.f, 0.f);
    for (int j = i; j < N_NODES * D / 4; j += stride) {
        ((float4*)g_acc_u)[j] = z;
        ((float4*)g_acc_v)[j] = z;
    }
    for (int j = i; j < N_NODES; j += stride) {
        g_cnt_s[j] = 0.f;
        g_cnt_d[j] = 0.f;
    }
}

template <bool EDGE>
__global__ __launch_bounds__(BLOCK, 1)
void mlp_mma_kernel(const float* __restrict__ ndata,
                    const float* __restrict__ edata,
                    const int* __restrict__ src,
                    const int* __restrict__ dst,
                    const float* __restrict__ W1,   // [192][128]
                    const float* __restrict__ b1,
                    const float* __restrict__ W2,   // [128][64]
                    const float* __restrict__ b2,
                    const float* __restrict__ gam,
                    const float* __restrict__ beta,
                    float* __restrict__ out,
                    int count) {
    extern __shared__ __align__(16) char smc[];
    const uint32_t sb = smem_u32(smc);
    const int tid = threadIdx.x;
    const int w = tid >> 5, l = tid & 31;

    // ---- stage weights transposed to [n][k] bf16 hi/lo ----
    for (int i = tid; i < IN_F * HID; i += BLOCK) {
        int k = i >> 7, n = i & 127;
        float v = W1[i];
        __nv_bfloat16 h = __float2bfloat16_rn(v);
        __nv_bfloat16 lo = __float2bfloat16_rn(v - __bfloat162float(h));
        uint32_t o = (uint32_t)(n * W1STR + k) * 2;
        *(__nv_bfloat16*)(smc + W1H_OFF + o) = h;
        *(__nv_bfloat16*)(smc + W1L_OFF + o) = lo;
    }
    for (int i = tid; i < HID * D; i += BLOCK) {
        int k = i >> 6, n = i & 63;
        float v = W2[i];
        __nv_bfloat16 h = __float2bfloat16_rn(v);
        __nv_bfloat16 lo = __float2bfloat16_rn(v - __bfloat162float(h));
        uint32_t o = (uint32_t)(n * W2STR + k) * 2;
        *(__nv_bfloat16*)(smc + W2H_OFF + o) = h;
        *(__nv_bfloat16*)(smc + W2L_OFF + o) = lo;
    }
    float* b1s = (float*)(smc + B1_OFF);
    float* b2s = (float*)(smc + B2_OFF);
    float* gs = (float*)(smc + G_OFF);
    float* bts = (float*)(smc + BETA_OFF);
    float* rs = (float*)(smc + RSUM_OFF);
    float* rq = (float*)(smc + RSQ_OFF);
    for (int i = tid; i < HID; i += BLOCK) b1s[i] = b1[i];
    for (int i = tid; i < D; i += BLOCK) {
        b2s[i] = b2[i];
        gs[i] = gam[i];
        bts[i] = beta[i];
    }
    __syncthreads();

    const float4* nd4 = (const float4*)ndata;
    const float4* ed4 = (const float4*)edata;

    // lane-invariant ldmatrix address pieces
    const int am = l >> 3;                     // matrix id 0..3
    const int g = l >> 2, t = l & 3;
    const int mw = w >> 3, nw = w & 7;         // 2 m-warps x 8 n-warps (both GEMMs)
    const uint32_t aoff1 = (uint32_t)((mw * 32 + (am & 1) * 8 + (l & 7)) * XSTR + (am >> 1) * 8) * 2;
    const uint32_t boff1 = (uint32_t)((nw * 16 + (am >> 1) * 8 + (l & 7)) * W1STR + (am & 1) * 8) * 2;
    const uint32_t aoff2 = (uint32_t)((mw * 32 + (am & 1) * 8 + (l & 7)) * HSTR + (am >> 1) * 8) * 2;
    uint32_t boff2;
    if (l < 8)        boff2 = (uint32_t)((nw * 8 + l) * W2STR) * 2;
    else if (l < 16)  boff2 = (uint32_t)((nw * 8 + (l - 8)) * W2STR + 8) * 2;
    else              boff2 = 0;

    const int ntiles = (count + TM - 1) / TM;
    for (int tile = blockIdx.x; tile < ntiles; tile += gridDim.x) {
        const int e0 = tile * TM;

        // ---- gather X[64][192] fp32 -> bf16 hi/lo smem ----
        #pragma unroll
        for (int jj = 0; jj < 6; jj++) {
            int j = tid + jj * BLOCK;          // 0..3071
            int e = j / 48, seg = j % 48;
            int idx = e0 + e;
            float4 v = make_float4(0.f, 0.f, 0.f, 0.f);
            if (EDGE || idx < count) {
                if (EDGE) {
                    if (seg < 16)      v = nd4[(size_t)src[idx] * 16 + seg];
                    else if (seg < 32) v = nd4[(size_t)dst[idx] * 16 + (seg - 16)];
                    else               v = ed4[(size_t)idx * 16 + (seg - 32)];
                } else {
                    if (seg < 16) {
                        float inv = 1.f / fmaxf(g_cnt_s[idx], 1.f);
                        float4 a = ((const float4*)g_acc_u)[(size_t)idx * 16 + seg];
                        v = make_float4(a.x * inv, a.y * inv, a.z * inv, a.w * inv);
                    } else if (seg < 32) {
                        float inv = 1.f / fmaxf(g_cnt_d[idx], 1.f);
                        float4 a = ((const float4*)g_acc_v)[(size_t)idx * 16 + (seg - 16)];
                        v = make_float4(a.x * inv, a.y * inv, a.z * inv, a.w * inv);
                    } else {
                        v = nd4[(size_t)idx * 16 + (seg - 32)];
                    }
                }
            }
            uint32_t h01, l01, h23, l23;
            split2(v.x, v.y, h01, l01);
            split2(v.z, v.w, h23, l23);
            uint32_t o = (uint32_t)(e * XSTR) * 2 + (uint32_t)seg * 8;
            *(uint2*)(smc + XH_OFF + o) = make_uint2(h01, h23);
            *(uint2*)(smc + XL_OFF + o) = make_uint2(l01, l23);
        }
        __syncthreads();

        // ---- GEMM1: C1[64][128] = X @ W1 (3-pass split bf16) ----
        float c1[2][2][4];
        #pragma unroll
        for (int mi = 0; mi < 2; mi++)
            #pragma unroll
            for (int ni = 0; ni < 2; ni++)
                #pragma unroll
                for (int q = 0; q < 4; q++) c1[mi][ni][q] = 0.f;
        #pragma unroll 2
        for (int ks = 0; ks < 12; ks++) {
            const uint32_t ko = (uint32_t)ks * 32;
            uint32_t ah[2][4], al[2][4], bh[4], bl[4];
            ldsm4(ah[0], sb + XH_OFF + aoff1 + ko);
            ldsm4(ah[1], sb + XH_OFF + aoff1 + 16 * XSTR * 2 + ko);
            ldsm4(al[0], sb + XL_OFF + aoff1 + ko);
            ldsm4(al[1], sb + XL_OFF + aoff1 + 16 * XSTR * 2 + ko);
            ldsm4(bh, sb + W1H_OFF + boff1 + ko);
            ldsm4(bl, sb + W1L_OFF + boff1 + ko);
            #pragma unroll
            for (int mi = 0; mi < 2; mi++)
                #pragma unroll
                for (int ni = 0; ni < 2; ni++) {
                    mma16816(c1[mi][ni], ah[mi], bh + ni * 2);
                    mma16816(c1[mi][ni], ah[mi], bl + ni * 2);
                    mma16816(c1[mi][ni], al[mi], bh + ni * 2);
                }
        }

        // ---- epilogue1: +b1, gelu, split -> H hi/lo smem ----
        #pragma unroll
        for (int mi = 0; mi < 2; mi++)
            #pragma unroll
            for (int ni = 0; ni < 2; ni++) {
                int colb = nw * 16 + ni * 8 + t * 2;
                #pragma unroll
                for (int h = 0; h < 2; h++) {
                    int r = mw * 32 + mi * 16 + g + h * 8;
                    float v0 = gelu_tanh(c1[mi][ni][2 * h] + b1s[colb]);
                    float v1 = gelu_tanh(c1[mi][ni][2 * h + 1] + b1s[colb + 1]);
                    uint32_t hi, lo;
                    split2(v0, v1, hi, lo);
                    uint32_t o = (uint32_t)(r * HSTR + colb) * 2;
                    *(uint32_t*)(smc + HH_OFF + o) = hi;
                    *(uint32_t*)(smc + HL_OFF + o) = lo;
                }
            }
        if (tid < TM) { rs[tid] = 0.f; rq[tid] = 0.f; }
        __syncthreads();

        // ---- GEMM2: C2[64][64] = H @ W2 (3-pass) ----
        float c2[2][4];
        #pragma unroll
        for (int mi = 0; mi < 2; mi++)
            #pragma unroll
            for (int q = 0; q < 4; q++) c2[mi][q] = 0.f;
        #pragma unroll 2
        for (int ks = 0; ks < 8; ks++) {
            const uint32_t ko = (uint32_t)ks * 32;
            uint32_t ah[2][4], al[2][4], bh[2], bl[2];
            ldsm4(ah[0], sb + HH_OFF + aoff2 + ko);
            ldsm4(ah[1], sb + HH_OFF + aoff2 + 16 * HSTR * 2 + ko);
            ldsm4(al[0], sb + HL_OFF + aoff2 + ko);
            ldsm4(al[1], sb + HL_OFF + aoff2 + 16 * HSTR * 2 + ko);
            ldsm2(bh, sb + W2H_OFF + boff2 + ko);
            ldsm2(bl, sb + W2L_OFF + boff2 + ko);
            #pragma unroll
            for (int mi = 0; mi < 2; mi++) {
                mma16816(c2[mi], ah[mi], bh);
                mma16816(c2[mi], ah[mi], bl);
                mma16816(c2[mi], al[mi], bh);
            }
        }

        // ---- LN partials (cross-warp via smem atomics) ----
        const int colb2 = nw * 8 + t * 2;
        float vv[2][2][2];
        #pragma unroll
        for (int mi = 0; mi < 2; mi++)
            #pragma unroll
            for (int h = 0; h < 2; h++) {
                float v0 = c2[mi][2 * h] + b2s[colb2];
                float v1 = c2[mi][2 * h + 1] + b2s[colb2 + 1];
                vv[mi][h][0] = v0;
                vv[mi][h][1] = v1;
                float s = v0 + v1, q = v0 * v0 + v1 * v1;
                s += __shfl_xor_sync(0xffffffffu, s, 1);
                q += __shfl_xor_sync(0xffffffffu, q, 1);
                s += __shfl_xor_sync(0xffffffffu, s, 2);
                q += __shfl_xor_sync(0xffffffffu, q, 2);
                if (t == 0) {
                    int r = mw * 32 + mi * 16 + g + h * 8;
                    atomicAdd(&rs[r], s);
                    atomicAdd(&rq[r], q);
                }
            }
        __syncthreads();

        // ---- normalize + writeout (+ scatter for EDGE) ----
        #pragma unroll
        for (int mi = 0; mi < 2; mi++)
            #pragma unroll
            for (int h = 0; h < 2; h++) {
                int r = mw * 32 + mi * 16 + g + h * 8;
                int idx = e0 + r;
                if (EDGE || idx < count) {
                    float mean = rs[r] * (1.f / 64.f);
                    float var = rq[r] * (1.f / 64.f) - mean * mean;
                    float rstd = rsqrtf(var + 1e-5f);
                    float o0 = (vv[mi][h][0] - mean) * rstd * gs[colb2] + bts[colb2];
                    float o1 = (vv[mi][h][1] - mean) * rstd * gs[colb2 + 1] + bts[colb2 + 1];
                    *(float2*)(out + (size_t)idx * D + colb2) = make_float2(o0, o1);
                    if (EDGE) {
                        int sN = src[idx], dN = dst[idx];
                        red_add_v2(g_acc_u + (size_t)sN * D + colb2, o0, o1);
                        red_add_v2(g_acc_v + (size_t)dN * D + colb2, o0, o1);
                        if (nw == 0 && t == 0) {
                            atomicAdd(&g_cnt_s[sN], 1.f);
                            atomicAdd(&g_cnt_d[dN], 1.f);
                        }
                    }
                }
            }
        __syncthreads();
    }
}

extern "C" void kernel_launch(void* const* d_in, const int* in_sizes, int n_in,
                              void* d_out, int out_size) {
    const float* ndata = (const float*)d_in[0];
    const float* edata = (const float*)d_in[1];
    const int* src = (const int*)d_in[2];
    const int* dst = (const int*)d_in[3];
    const float* eW1 = (const float*)d_in[4];
    const float* eb1 = (const float*)d_in[5];
    const float* eW2 = (const float*)d_in[6];
    const float* eb2 = (const float*)d_in[7];
    const float* eg = (const float*)d_in[8];
    const float* ebeta = (const float*)d_in[9];
    const float* nW1 = (const float*)d_in[10];
    const float* nb1 = (const float*)d_in[11];
    const float* nW2 = (const float*)d_in[12];
    const float* nb2 = (const float*)d_in[13];
    const float* ng = (const float*)d_in[14];
    const float* nbeta = (const float*)d_in[15];

    float* out = (float*)d_out;
    float* out_nodes = out;
    float* out_edges = out + (size_t)N_NODES * D;

    void (*kE)(const float*, const float*, const int*, const int*,
               const float*, const float*, const float*, const float*,
               const float*, const float*, float*, int) = mlp_mma_kernel<true>;
    void (*kN)(const float*, const float*, const int*, const int*,
               const float*, const float*, const float*, const float*,
               const float*, const float*, float*, int) = mlp_mma_kernel<false>;
    cudaFuncSetAttribute((const void*)kE, cudaFuncAttributeMaxDynamicSharedMemorySize, SMEM_BYTES);
    cudaFuncSetAttribute((const void*)kN, cudaFuncAttributeMaxDynamicSharedMemorySize, SMEM_BYTES);

    zero_scratch_kernel<<<1024, 256>>>();
    kE<<<NBLK, BLOCK, SMEM_BYTES>>>(ndata, edata, src, dst,
                                    eW1, eb1, eW2, eb2, eg, ebeta,
                                    out_edges, N_EDGES);
    kN<<<NBLK, BLOCK, SMEM_BYTES>>>(ndata, nullptr, nullptr, nullptr,
                                    nW1, nb1, nW2, nb2, ng, nbeta,
                                    out_nodes, N_NODES);
}

// round 10
// speedup vs baseline: 6.6326x; 1.1749x over previous
#include <cuda_runtime.h>
#include <cuda_fp16.h>
#include <math.h>
#include <stdint.h>
#include <stddef.h>

#define N_NODES 50000
#define N_EDGES 800000
#define D 64
#define HID 128
#define IN_F 192
#define TM 64
#define BLOCK 512
#define NBLK 152

// padded fp16 row strides (row byte base steps by 16 mod 128 -> conflict-free ldmatrix)
#define XSTR 200     // K=192 + 8 pad
#define HSTR 136     // K=128 + 8 pad
#define W1STR 200
#define W2STR 136

// ---- shared memory byte offsets ----
#define W1H_OFF 0            // [128 n][200 k] fp16 = 51200
#define W1L_OFF 51200
#define W2H_OFF 102400       // [64 n][136 k] fp16 = 17408
#define W2L_OFF 119808
#define X_OFF 137216         // [64 m][200 k] fp16 = 25600 (single buffer)
#define H_OFF 162816         // [64 m][136 k] fp16 = 17408 (single buffer)
#define B1_OFF 180224        // b1[128] f32
#define B2_OFF 180736        // b2[64] f32
#define G_OFF 180992
#define BETA_OFF 181248
#define RSUM_OFF 181504      // per-row LN partial sum [64]
#define RSQ_OFF 181760       // per-row LN partial sumsq [64]
#define SMEM_BYTES 182016

// scratch for segment-mean aggregation
__device__ __align__(16) float g_acc_u[N_NODES * D];
__device__ __align__(16) float g_acc_v[N_NODES * D];
__device__ float g_cnt_s[N_NODES];
__device__ float g_cnt_d[N_NODES];

// ---------------- helpers ----------------
__device__ __forceinline__ uint32_t smem_u32(const void* p) {
    uint32_t a;
    asm("{ .reg .u64 t; cvta.to.shared.u64 t, %1; cvt.u32.u64 %0, t; }" : "=r"(a) : "l"(p));
    return a;
}
__device__ __forceinline__ void ldsm4(uint32_t* r, uint32_t addr) {
    asm volatile("ldmatrix.sync.aligned.m8n8.x4.shared.b16 {%0,%1,%2,%3}, [%4];"
                 : "=r"(r[0]), "=r"(r[1]), "=r"(r[2]), "=r"(r[3]) : "r"(addr));
}
__device__ __forceinline__ void ldsm2(uint32_t* r, uint32_t addr) {
    asm volatile("ldmatrix.sync.aligned.m8n8.x2.shared.b16 {%0,%1}, [%2];"
                 : "=r"(r[0]), "=r"(r[1]) : "r"(addr));
}
__device__ __forceinline__ void mma16816(float* d, const uint32_t* a, const uint32_t* b) {
    asm volatile("mma.sync.aligned.m16n8k16.row.col.f32.f16.f16.f32 "
                 "{%0,%1,%2,%3}, {%4,%5,%6,%7}, {%8,%9}, {%0,%1,%2,%3};"
                 : "+f"(d[0]), "+f"(d[1]), "+f"(d[2]), "+f"(d[3])
                 : "r"(a[0]), "r"(a[1]), "r"(a[2]), "r"(a[3]), "r"(b[0]), "r"(b[1]));
}
__device__ __forceinline__ uint32_t pack_h2(float a, float b) {
    __half2 h = __floats2half2_rn(a, b);
    return *reinterpret_cast<uint32_t*>(&h);
}
__device__ __forceinline__ float gelu_tanh(float x) {
    float x3 = x * x * x;
    return 0.5f * x * (1.0f + tanhf(0.7978845608028654f * (x + 0.044715f * x3)));
}
__device__ __forceinline__ void red_add_v2(float* addr, float a, float b) {
    asm volatile("red.global.add.v2.f32 [%0], {%1,%2};"
                 :: "l"(addr), "f"(a), "f"(b) : "memory");
}

__global__ void zero_scratch_kernel() {
    int i = blockIdx.x * blockDim.x + threadIdx.x;
    int stride = gridDim.x * blockDim.x;
    const float4 z = make_float4(0.f, 0.f, 0.f, 0.f);
    for (int j = i; j < N_NODES * D / 4; j += stride) {
        ((float4*)g_acc_u)[j] = z;
        ((float4*)g_acc_v)[j] = z;
    }
    for (int j = i; j < N_NODES; j += stride) {
        g_cnt_s[j] = 0.f;
        g_cnt_d[j] = 0.f;
    }
}

template <bool EDGE>
__global__ __launch_bounds__(BLOCK, 1)
void mlp_mma_kernel(const float* __restrict__ ndata,
                    const float* __restrict__ edata,
                    const int* __restrict__ src,
                    const int* __restrict__ dst,
                    const float* __restrict__ W1,   // [192][128]
                    const float* __restrict__ b1,
                    const float* __restrict__ W2,   // [128][64]
                    const float* __restrict__ b2,
                    const float* __restrict__ gam,
                    const float* __restrict__ beta,
                    float* __restrict__ out,
                    int count) {
    extern __shared__ __align__(16) char smc[];
    const uint32_t sb = smem_u32(smc);
    const int tid = threadIdx.x;
    const int w = tid >> 5, l = tid & 31;

    // ---- stage weights transposed to [n][k], fp16 split hi/lo ----
    for (int i = tid; i < IN_F * HID; i += BLOCK) {
        int k = i >> 7, n = i & 127;
        float v = W1[i];
        __half h = __float2half_rn(v);
        __half lo = __float2half_rn(v - __half2float(h));
        uint32_t o = (uint32_t)(n * W1STR + k) * 2;
        *(__half*)(smc + W1H_OFF + o) = h;
        *(__half*)(smc + W1L_OFF + o) = lo;
    }
    for (int i = tid; i < HID * D; i += BLOCK) {
        int k = i >> 6, n = i & 63;
        float v = W2[i];
        __half h = __float2half_rn(v);
        __half lo = __float2half_rn(v - __half2float(h));
        uint32_t o = (uint32_t)(n * W2STR + k) * 2;
        *(__half*)(smc + W2H_OFF + o) = h;
        *(__half*)(smc + W2L_OFF + o) = lo;
    }
    float* b1s = (float*)(smc + B1_OFF);
    float* b2s = (float*)(smc + B2_OFF);
    float* gs = (float*)(smc + G_OFF);
    float* bts = (float*)(smc + BETA_OFF);
    float* rs = (float*)(smc + RSUM_OFF);
    float* rq = (float*)(smc + RSQ_OFF);
    for (int i = tid; i < HID; i += BLOCK) b1s[i] = b1[i];
    for (int i = tid; i < D; i += BLOCK) {
        b2s[i] = b2[i];
        gs[i] = gam[i];
        bts[i] = beta[i];
    }
    __syncthreads();

    const float4* nd4 = (const float4*)ndata;
    const float4* ed4 = (const float4*)edata;

    // lane-invariant ldmatrix address pieces
    const int am = l >> 3;                     // matrix id 0..3
    const int g = l >> 2, t = l & 3;
    const int mw = w >> 3, nw = w & 7;         // 2 m-warps x 8 n-warps
    const uint32_t aoff1 = (uint32_t)((mw * 32 + (am & 1) * 8 + (l & 7)) * XSTR + (am >> 1) * 8) * 2;
    const uint32_t boff1 = (uint32_t)((nw * 16 + (am >> 1) * 8 + (l & 7)) * W1STR + (am & 1) * 8) * 2;
    const uint32_t aoff2 = (uint32_t)((mw * 32 + (am & 1) * 8 + (l & 7)) * HSTR + (am >> 1) * 8) * 2;
    uint32_t boff2;
    if (l < 8)        boff2 = (uint32_t)((nw * 8 + l) * W2STR) * 2;
    else if (l < 16)  boff2 = (uint32_t)((nw * 8 + (l - 8)) * W2STR + 8) * 2;
    else              boff2 = 0;

    const int ntiles = (count + TM - 1) / TM;
    for (int tile = blockIdx.x; tile < ntiles; tile += gridDim.x) {
        const int e0 = tile * TM;

        // ---- gather X[64][192] fp32 -> fp16 smem (single buffer) ----
        #pragma unroll
        for (int jj = 0; jj < 6; jj++) {
            int j = tid + jj * BLOCK;          // 0..3071
            int e = j / 48, seg = j % 48;
            int idx = e0 + e;
            float4 v = make_float4(0.f, 0.f, 0.f, 0.f);
            if (EDGE || idx < count) {
                if (EDGE) {
                    if (seg < 16)      v = nd4[(size_t)src[idx] * 16 + seg];
                    else if (seg < 32) v = nd4[(size_t)dst[idx] * 16 + (seg - 16)];
                    else               v = ed4[(size_t)idx * 16 + (seg - 32)];
                } else {
                    if (seg < 16) {
                        float inv = 1.f / fmaxf(g_cnt_s[idx], 1.f);
                        float4 a = ((const float4*)g_acc_u)[(size_t)idx * 16 + seg];
                        v = make_float4(a.x * inv, a.y * inv, a.z * inv, a.w * inv);
                    } else if (seg < 32) {
                        float inv = 1.f / fmaxf(g_cnt_d[idx], 1.f);
                        float4 a = ((const float4*)g_acc_v)[(size_t)idx * 16 + (seg - 16)];
                        v = make_float4(a.x * inv, a.y * inv, a.z * inv, a.w * inv);
                    } else {
                        v = nd4[(size_t)idx * 16 + (seg - 32)];
                    }
                }
            }
            uint32_t o = (uint32_t)(e * XSTR) * 2 + (uint32_t)seg * 8;
            *(uint2*)(smc + X_OFF + o) = make_uint2(pack_h2(v.x, v.y), pack_h2(v.z, v.w));
        }
        __syncthreads();

        // ---- GEMM1: C1[64][128] = X @ (W1hi + W1lo), 2-pass fp16 ----
        float c1[2][2][4];
        #pragma unroll
        for (int mi = 0; mi < 2; mi++)
            #pragma unroll
            for (int ni = 0; ni < 2; ni++)
                #pragma unroll
                for (int q = 0; q < 4; q++) c1[mi][ni][q] = 0.f;
        #pragma unroll 2
        for (int ks = 0; ks < 12; ks++) {
            const uint32_t ko = (uint32_t)ks * 32;
            uint32_t a[2][4], bh[4], bl[4];
            ldsm4(a[0], sb + X_OFF + aoff1 + ko);
            ldsm4(a[1], sb + X_OFF + aoff1 + 16 * XSTR * 2 + ko);
            ldsm4(bh, sb + W1H_OFF + boff1 + ko);
            ldsm4(bl, sb + W1L_OFF + boff1 + ko);
            #pragma unroll
            for (int mi = 0; mi < 2; mi++)
                #pragma unroll
                for (int ni = 0; ni < 2; ni++) {
                    mma16816(c1[mi][ni], a[mi], bh + ni * 2);
                    mma16816(c1[mi][ni], a[mi], bl + ni * 2);
                }
        }

        // ---- epilogue1: +b1, gelu -> H fp16 smem ----
        #pragma unroll
        for (int mi = 0; mi < 2; mi++)
            #pragma unroll
            for (int ni = 0; ni < 2; ni++) {
                int colb = nw * 16 + ni * 8 + t * 2;
                #pragma unroll
                for (int h = 0; h < 2; h++) {
                    int r = mw * 32 + mi * 16 + g + h * 8;
                    float v0 = gelu_tanh(c1[mi][ni][2 * h] + b1s[colb]);
                    float v1 = gelu_tanh(c1[mi][ni][2 * h + 1] + b1s[colb + 1]);
                    *(uint32_t*)(smc + H_OFF + (uint32_t)(r * HSTR + colb) * 2) = pack_h2(v0, v1);
                }
            }
        if (tid < TM) { rs[tid] = 0.f; rq[tid] = 0.f; }
        __syncthreads();

        // ---- GEMM2: C2[64][64] = H @ (W2hi + W2lo), 2-pass ----
        float c2[2][4];
        #pragma unroll
        for (int mi = 0; mi < 2; mi++)
            #pragma unroll
            for (int q = 0; q < 4; q++) c2[mi][q] = 0.f;
        #pragma unroll 2
        for (int ks = 0; ks < 8; ks++) {
            const uint32_t ko = (uint32_t)ks * 32;
            uint32_t a[2][4], bh[2], bl[2];
            ldsm4(a[0], sb + H_OFF + aoff2 + ko);
            ldsm4(a[1], sb + H_OFF + aoff2 + 16 * HSTR * 2 + ko);
            ldsm2(bh, sb + W2H_OFF + boff2 + ko);
            ldsm2(bl, sb + W2L_OFF + boff2 + ko);
            #pragma unroll
            for (int mi = 0; mi < 2; mi++) {
                mma16816(c2[mi], a[mi], bh);
                mma16816(c2[mi], a[mi], bl);
            }
        }

        // ---- LN partials (cross-warp via smem atomics) ----
        const int colb2 = nw * 8 + t * 2;
        float vv[2][2][2];
        #pragma unroll
        for (int mi = 0; mi < 2; mi++)
            #pragma unroll
            for (int h = 0; h < 2; h++) {
                float v0 = c2[mi][2 * h] + b2s[colb2];
                float v1 = c2[mi][2 * h + 1] + b2s[colb2 + 1];
                vv[mi][h][0] = v0;
                vv[mi][h][1] = v1;
                float s = v0 + v1, q = v0 * v0 + v1 * v1;
                s += __shfl_xor_sync(0xffffffffu, s, 1);
                q += __shfl_xor_sync(0xffffffffu, q, 1);
                s += __shfl_xor_sync(0xffffffffu, s, 2);
                q += __shfl_xor_sync(0xffffffffu, q, 2);
                if (t == 0) {
                    int r = mw * 32 + mi * 16 + g + h * 8;
                    atomicAdd(&rs[r], s);
                    atomicAdd(&rq[r], q);
                }
            }
        __syncthreads();

        // ---- normalize + writeout (+ scatter for EDGE) ----
        #pragma unroll
        for (int mi = 0; mi < 2; mi++)
            #pragma unroll
            for (int h = 0; h < 2; h++) {
                int r = mw * 32 + mi * 16 + g + h * 8;
                int idx = e0 + r;
                if (EDGE || idx < count) {
                    float mean = rs[r] * (1.f / 64.f);
                    float var = rq[r] * (1.f / 64.f) - mean * mean;
                    float rstd = rsqrtf(var + 1e-5f);
                    float o0 = (vv[mi][h][0] - mean) * rstd * gs[colb2] + bts[colb2];
                    float o1 = (vv[mi][h][1] - mean) * rstd * gs[colb2 + 1] + bts[colb2 + 1];
                    *(float2*)(out + (size_t)idx * D + colb2) = make_float2(o0, o1);
                    if (EDGE) {
                        int sN = src[idx], dN = dst[idx];
                        red_add_v2(g_acc_u + (size_t)sN * D + colb2, o0, o1);
                        red_add_v2(g_acc_v + (size_t)dN * D + colb2, o0, o1);
                        if (nw == 0 && t == 0) {
                            atomicAdd(&g_cnt_s[sN], 1.f);
                            atomicAdd(&g_cnt_d[dN], 1.f);
                        }
                    }
                }
            }
        __syncthreads();
    }
}

extern "C" void kernel_launch(void* const* d_in, const int* in_sizes, int n_in,
                              void* d_out, int out_size) {
    const float* ndata = (const float*)d_in[0];
    const float* edata = (const float*)d_in[1];
    const int* src = (const int*)d_in[2];
    const int* dst = (const int*)d_in[3];
    const float* eW1 = (const float*)d_in[4];
    const float* eb1 = (const float*)d_in[5];
    const float* eW2 = (const float*)d_in[6];
    const float* eb2 = (const float*)d_in[7];
    const float* eg = (const float*)d_in[8];
    const float* ebeta = (const float*)d_in[9];
    const float* nW1 = (const float*)d_in[10];
    const float* nb1 = (const float*)d_in[11];
    const float* nW2 = (const float*)d_in[12];
    const float* nb2 = (const float*)d_in[13];
    const float* ng = (const float*)d_in[14];
    const float* nbeta = (const float*)d_in[15];

    float* out = (float*)d_out;
    float* out_nodes = out;
    float* out_edges = out + (size_t)N_NODES * D;

    void (*kE)(const float*, const float*, const int*, const int*,
               const float*, const float*, const float*, const float*,
               const float*, const float*, float*, int) = mlp_mma_kernel<true>;
    void (*kN)(const float*, const float*, const int*, const int*,
               const float*, const float*, const float*, const float*,
               const float*, const float*, float*, int) = mlp_mma_kernel<false>;
    cudaFuncSetAttribute((const void*)kE, cudaFuncAttributeMaxDynamicSharedMemorySize, SMEM_BYTES);
    cudaFuncSetAttribute((const void*)kN, cudaFuncAttributeMaxDynamicSharedMemorySize, SMEM_BYTES);

    zero_scratch_kernel<<<1024, 256>>>();
    kE<<<NBLK, BLOCK, SMEM_BYTES>>>(ndata, edata, src, dst,
                                    eW1, eb1, eW2, eb2, eg, ebeta,
                                    out_edges, N_EDGES);
    kN<<<NBLK, BLOCK, SMEM_BYTES>>>(ndata, nullptr, nullptr, nullptr,
                                    nW1, nb1, nW2, nb2, ng, nbeta,
                                    out_nodes, N_NODES);
}